// round 10
// baseline (speedup 1.0000x reference)
#include <cuda_runtime.h>
#include <math.h>

#define SEQ   2048
#define SEQ2  (SEQ / 2)
#define SEQ4  (SEQ / 4)
#define SEQ8  (SEQ / 8)       // 256 blocked-8 steps
#define EMB   1024
#define HID   2048
#define VOCAB 50257
#define WSTRIDE (EMB + HID)   // 3072, row stride of W_i2h

#define NCTA 128
#define NREP 4

// ---------------- scratch (device globals: allocation-free rule) ----------
__device__ __align__(16) float g_X [SEQ  * HID];      // 16 MB
__device__ __align__(16) float g_X2[SEQ2 * HID];      //  8 MB
__device__ __align__(16) float g_X4[SEQ4 * HID];      //  4 MB
__device__ __align__(16) float g_X8[SEQ8 * HID];      //  2 MB
__device__ __align__(16) float g_W2[HID * HID];       // 16 MB
__device__ __align__(16) float g_W4[HID * HID];       // 16 MB
__device__ __align__(16) float g_W8[HID * HID];       // 16 MB
__device__ __align__(16) float g_hrep[2][NREP][HID];
__device__ unsigned g_cnt;
__device__ int g_tok64 = 0;

// ---------------- memory-order / packed-math helpers ----------------------
__device__ __forceinline__ unsigned ld_relaxed(const unsigned* p) {
    unsigned v;
    asm volatile("ld.relaxed.gpu.global.u32 %0, [%1];" : "=r"(v) : "l"(p) : "memory");
    return v;
}
__device__ __forceinline__ void red_add_release(unsigned* p, unsigned v) {
    asm volatile("red.release.gpu.global.add.u32 [%0], %1;" :: "l"(p), "r"(v) : "memory");
}
__device__ __forceinline__ void fence_acq() {
    asm volatile("fence.acq_rel.gpu;" ::: "memory");
}
__device__ __forceinline__ unsigned long long pack2(float lo, float hi) {
    unsigned long long r;
    asm("mov.b64 %0, {%1, %2};" : "=l"(r) : "f"(lo), "f"(hi));
    return r;
}
__device__ __forceinline__ void unpack2(float& lo, float& hi, unsigned long long v) {
    asm("mov.b64 {%0, %1}, %2;" : "=f"(lo), "=f"(hi) : "l"(v));
}
__device__ __forceinline__ void ffma2(unsigned long long& acc,
                                      unsigned long long a, unsigned long long b) {
    asm("fma.rn.f32x2 %0, %1, %2, %0;" : "+l"(acc) : "l"(a), "l"(b));
}

// ---------------- per-launch reset ----------------------------------------
__global__ void reset_kernel() {
    if (threadIdx.x == 0) g_cnt = 0;
}

// ---------------- token dtype detection -----------------------------------
__global__ void detect_tok_kernel(const int* __restrict__ p) {
    __shared__ int bad;
    if (threadIdx.x == 0) bad = 0;
    __syncthreads();
    int mybad = 0;
    for (int i = threadIdx.x; i < SEQ / 2; i += blockDim.x) {
        int lo = p[2 * i];
        int hi = p[2 * i + 1];
        if (hi != 0 || lo < 0 || lo >= VOCAB) mybad = 1;
    }
    if (mybad) atomicOr(&bad, 1);
    __syncthreads();
    if (threadIdx.x == 0) g_tok64 = bad ? 0 : 1;
}

// =================== GEMM tiles: 128x128x16, 256 thr, 8x8 micro ==========
#define BM 128
#define BN 128
#define BK 16
#define GTHREADS 256

// Packed-f32x2 micro-kernel body: consumes As/Bs tile, accumulates into
// acc2[ip][j] where .lo = row 2*ip, .hi = row 2*ip+1 of the 8x8 micro-tile.
__device__ __forceinline__ void micro_ffma2(
    const float (*As)[BM + 4], const float (*Bs)[BN + 4],
    int ty, int tx, unsigned long long acc2[4][8]) {
#pragma unroll
    for (int k = 0; k < BK; k++) {
        float a[8], b[8];
        *(float4*)&a[0] = *(const float4*)&As[k][ty * 8];
        *(float4*)&a[4] = *(const float4*)&As[k][ty * 8 + 4];
        *(float4*)&b[0] = *(const float4*)&Bs[k][tx * 8];
        *(float4*)&b[4] = *(const float4*)&Bs[k][tx * 8 + 4];
        unsigned long long ap[4];
#pragma unroll
        for (int ip = 0; ip < 4; ip++) ap[ip] = pack2(a[2 * ip], a[2 * ip + 1]);
#pragma unroll
        for (int j = 0; j < 8; j++) {
            unsigned long long bb = pack2(b[j], b[j]);
#pragma unroll
            for (int ip = 0; ip < 4; ip++)
                ffma2(acc2[ip][j], ap[ip], bb);
        }
    }
}

// ---------------- X = E @ W_e^T + b ---------------------------------------
__global__ void __launch_bounds__(GTHREADS, 1)
gemm_x_kernel(const int* __restrict__ toks,
              const float* __restrict__ emb,
              const float* __restrict__ Wi2h,
              const float* __restrict__ bias) {
    __shared__ __align__(16) float As[BK][BM + 4];
    __shared__ __align__(16) float Bs[BK][BN + 4];
    __shared__ int stok[BM];

    const int tid = threadIdx.x;
    const int t0 = blockIdx.y * BM;
    const int r0 = blockIdx.x * BN;
    const int tok64 = g_tok64;

    if (tid < BM) {
        int t = t0 + tid;
        stok[tid] = tok64 ? toks[2 * t] : toks[t];
    }
    __syncthreads();

    const int tx = tid & 15;
    const int ty = tid >> 4;

    unsigned long long acc2[4][8];
#pragma unroll
    for (int ip = 0; ip < 4; ip++)
#pragma unroll
        for (int j = 0; j < 8; j++) acc2[ip][j] = 0ull;

    for (int kk = 0; kk < EMB; kk += BK) {
#pragma unroll
        for (int i = 0; i < 2; i++) {
            int v = tid + i * GTHREADS;
            int m = v >> 2;
            int k = (v & 3) << 2;
            float4 a = *(const float4*)&emb[(size_t)stok[m] * EMB + kk + k];
            As[k + 0][m] = a.x; As[k + 1][m] = a.y;
            As[k + 2][m] = a.z; As[k + 3][m] = a.w;
            float4 b = *(const float4*)&Wi2h[(size_t)(r0 + m) * WSTRIDE + kk + k];
            Bs[k + 0][m] = b.x; Bs[k + 1][m] = b.y;
            Bs[k + 2][m] = b.z; Bs[k + 3][m] = b.w;
        }
        __syncthreads();
        micro_ffma2(As, Bs, ty, tx, acc2);
        __syncthreads();
    }

    float bv[8];
#pragma unroll
    for (int j = 0; j < 8; j++) bv[j] = bias[r0 + tx * 8 + j];

#pragma unroll
    for (int ip = 0; ip < 4; ip++) {
        float o0[8], o1[8];
#pragma unroll
        for (int j = 0; j < 8; j++) {
            float lo, hi;
            unpack2(lo, hi, acc2[ip][j]);
            o0[j] = lo + bv[j];
            o1[j] = hi + bv[j];
        }
        int trow0 = t0 + ty * 8 + 2 * ip;
        *(float4*)&g_X[(size_t)trow0 * HID + r0 + tx * 8]     = *(float4*)&o0[0];
        *(float4*)&g_X[(size_t)trow0 * HID + r0 + tx * 8 + 4] = *(float4*)&o0[4];
        *(float4*)&g_X[(size_t)(trow0 + 1) * HID + r0 + tx * 8]     = *(float4*)&o1[0];
        *(float4*)&g_X[(size_t)(trow0 + 1) * HID + r0 + tx * 8 + 4] = *(float4*)&o1[4];
    }
}

// ---------------- generic square product: C = A @ A ------------------------
template <int ASTRIDE, int AOFF>
__global__ void __launch_bounds__(GTHREADS, 1)
gemm_sq_kernel(const float* __restrict__ A, float* __restrict__ C) {
    __shared__ __align__(16) float As[BK][BM + 4];
    __shared__ __align__(16) float Bs[BK][BN + 4];

    const int tid = threadIdx.x;
    const int i0 = blockIdx.y * BM;
    const int j0 = blockIdx.x * BN;

    const int tx = tid & 15;
    const int ty = tid >> 4;

    unsigned long long acc2[4][8];
#pragma unroll
    for (int ip = 0; ip < 4; ip++)
#pragma unroll
        for (int j = 0; j < 8; j++) acc2[ip][j] = 0ull;

    for (int kk = 0; kk < HID; kk += BK) {
#pragma unroll
        for (int i = 0; i < 2; i++) {
            int v = tid + i * GTHREADS;
            int m = v >> 2;
            int k = (v & 3) << 2;
            float4 a = *(const float4*)&A[(size_t)(i0 + m) * ASTRIDE + AOFF + kk + k];
            As[k + 0][m] = a.x; As[k + 1][m] = a.y;
            As[k + 2][m] = a.z; As[k + 3][m] = a.w;
        }
#pragma unroll
        for (int i = 0; i < 2; i++) {
            int v = tid + i * GTHREADS;
            int k = v >> 5;
            int j = (v & 31) << 2;
            float4 b = *(const float4*)&A[(size_t)(kk + k) * ASTRIDE + AOFF + j0 + j];
            *(float4*)&Bs[k][j] = b;
        }
        __syncthreads();
        micro_ffma2(As, Bs, ty, tx, acc2);
        __syncthreads();
    }

#pragma unroll
    for (int ip = 0; ip < 4; ip++) {
        float o0[8], o1[8];
#pragma unroll
        for (int j = 0; j < 8; j++) unpack2(o0[j], o1[j], acc2[ip][j]);
        int r = i0 + ty * 8 + 2 * ip;
        *(float4*)&C[(size_t)r * HID + j0 + tx * 8]     = *(float4*)&o0[0];
        *(float4*)&C[(size_t)r * HID + j0 + tx * 8 + 4] = *(float4*)&o0[4];
        *(float4*)&C[(size_t)(r + 1) * HID + j0 + tx * 8]     = *(float4*)&o1[0];
        *(float4*)&C[(size_t)(r + 1) * HID + j0 + tx * 8 + 4] = *(float4*)&o1[4];
    }
}

// ---------------- fold: Y[s] = W @ Xin[2s] + Xin[2s+1] ---------------------
template <int WSTRIDE_, int WOFF>
__global__ void __launch_bounds__(GTHREADS, 1)
gemm_fold_kernel(const float* __restrict__ W,
                 const float* __restrict__ Xin,
                 float* __restrict__ Y) {
    __shared__ __align__(16) float As[BK][BM + 4];
    __shared__ __align__(16) float Bs[BK][BN + 4];

    const int tid = threadIdx.x;
    const int s0 = blockIdx.y * BM;
    const int r0 = blockIdx.x * BN;

    const int tx = tid & 15;
    const int ty = tid >> 4;

    unsigned long long acc2[4][8];
#pragma unroll
    for (int ip = 0; ip < 4; ip++)
#pragma unroll
        for (int j = 0; j < 8; j++) acc2[ip][j] = 0ull;

    for (int kk = 0; kk < HID; kk += BK) {
#pragma unroll
        for (int i = 0; i < 2; i++) {
            int v = tid + i * GTHREADS;
            int m = v >> 2;
            int k = (v & 3) << 2;
            float4 a = *(const float4*)&Xin[(size_t)(2 * (s0 + m)) * HID + kk + k];
            As[k + 0][m] = a.x; As[k + 1][m] = a.y;
            As[k + 2][m] = a.z; As[k + 3][m] = a.w;
            float4 b = *(const float4*)&W[(size_t)(r0 + m) * WSTRIDE_ + WOFF + kk + k];
            Bs[k + 0][m] = b.x; Bs[k + 1][m] = b.y;
            Bs[k + 2][m] = b.z; Bs[k + 3][m] = b.w;
        }
        __syncthreads();
        micro_ffma2(As, Bs, ty, tx, acc2);
        __syncthreads();
    }

#pragma unroll
    for (int ip = 0; ip < 4; ip++) {
        int s = s0 + ty * 8 + 2 * ip;
#pragma unroll
        for (int half = 0; half < 2; half++) {
            int ss = s + half;
            float4 e0 = *(const float4*)&Xin[(size_t)(2 * ss + 1) * HID + r0 + tx * 8];
            float4 e1 = *(const float4*)&Xin[(size_t)(2 * ss + 1) * HID + r0 + tx * 8 + 4];
            float o[8];
#pragma unroll
            for (int j = 0; j < 8; j++) {
                float lo, hi;
                unpack2(lo, hi, acc2[ip][j]);
                o[j] = (half == 0 ? lo : hi);
            }
            o[0] += e0.x; o[1] += e0.y; o[2] += e0.z; o[3] += e0.w;
            o[4] += e1.x; o[5] += e1.y; o[6] += e1.z; o[7] += e1.w;
            *(float4*)&Y[(size_t)ss * HID + r0 + tx * 8]     = *(float4*)&o[0];
            *(float4*)&Y[(size_t)ss * HID + r0 + tx * 8 + 4] = *(float4*)&o[4];
        }
    }
}

// ---------------- persistent recurrence kernel (256 steps, W8/X8) ---------
#define ROWS_PER_CTA (HID / NCTA)  // 16
#define RTHREADS 512

__global__ void __launch_bounds__(RTHREADS, 1)
rnn_kernel(const float* __restrict__ Wh2o,
           const float* __restrict__ bh2o,
           float* __restrict__ out) {
    __shared__ __align__(16) float sh[HID];
    __shared__ float sred[64];

    const int tid = threadIdx.x;
    const int cta = blockIdx.x;
    const int r0  = cta * ROWS_PER_CTA;
    const int repl = cta & (NREP - 1);

    const int w = tid >> 5, l = tid & 31;
    const int grp = w & 3;
    const int q   = w >> 2;

    unsigned long long Wr[4][8];
#pragma unroll
    for (int rr = 0; rr < 4; rr++)
#pragma unroll
        for (int k = 0; k < 4; k++) {
            float4 wv = *(const float4*)&g_W8[
                (size_t)(r0 + 4 * grp + rr) * HID
                + (q << 9) + (l << 2) + (k << 7)];
            Wr[rr][2 * k]     = pack2(wv.x, wv.y);
            Wr[rr][2 * k + 1] = pack2(wv.z, wv.w);
        }

    for (int t = 0; t < SEQ8; t++) {
        float xv = 0.f;
        if (tid < ROWS_PER_CTA) xv = __ldcg(&g_X8[(size_t)t * HID + r0 + tid]);

        if (t > 0) {
            if (w == 0) {
                const unsigned tgt = (unsigned)t << 7;
                unsigned e;
                do { e = ld_relaxed(&g_cnt); }
                while (__any_sync(0xffffffffu, e < tgt));
                fence_acq();
            }
            __syncthreads();

            const float* hprev = g_hrep[(t - 1) & 1][repl];
            float4 ch = __ldcg((const float4*)&hprev[(w << 7) + (l << 2)]);
            *(float4*)&sh[(w << 7) + (l << 2)] = ch;
            __syncthreads();

            const float4* sh4 = (const float4*)sh;
            unsigned long long acc2[4];
#pragma unroll
            for (int rr = 0; rr < 4; rr++) acc2[rr] = 0ull;

#pragma unroll
            for (int k = 0; k < 4; k++) {
                float4 hv = sh4[(q << 7) + (k << 5) + l];
                unsigned long long h0 = pack2(hv.x, hv.y);
                unsigned long long h1 = pack2(hv.z, hv.w);
#pragma unroll
                for (int rr = 0; rr < 4; rr++) {
                    ffma2(acc2[rr], Wr[rr][2 * k],     h0);
                    ffma2(acc2[rr], Wr[rr][2 * k + 1], h1);
                }
            }

#pragma unroll
            for (int rr = 0; rr < 4; rr++) {
                float lo, hi;
                unpack2(lo, hi, acc2[rr]);
                float v = lo + hi;
                v += __shfl_xor_sync(0xffffffffu, v, 16);
                v += __shfl_xor_sync(0xffffffffu, v, 8);
                v += __shfl_xor_sync(0xffffffffu, v, 4);
                v += __shfl_xor_sync(0xffffffffu, v, 2);
                v += __shfl_xor_sync(0xffffffffu, v, 1);
                if (l == 0) sred[w * 4 + rr] = v;
            }
            __syncthreads();

            if (tid < ROWS_PER_CTA) {
                int g = tid >> 2, rr = tid & 3;
                float v = xv;
#pragma unroll
                for (int qq = 0; qq < 4; qq++)
                    v += sred[((qq << 2) | g) * 4 + rr];
#pragma unroll
                for (int r = 0; r < NREP; r++)
                    g_hrep[t & 1][r][r0 + tid] = v;
            }
        } else {
            if (tid < ROWS_PER_CTA) {
#pragma unroll
                for (int r = 0; r < NREP; r++)
                    g_hrep[0][r][r0 + tid] = xv;
            }
        }

        if (w == 0) {
            __syncwarp();
            if (l == 0) red_add_release(&g_cnt, 1u);
        }
    }

    // readout
    if (cta == 0) {
        if (w == 0) {
            const unsigned tgt = (unsigned)SEQ8 << 7;
            unsigned e;
            do { e = ld_relaxed(&g_cnt); }
            while (__any_sync(0xffffffffu, e < tgt));
            fence_acq();
        }
        __syncthreads();
        const float* hf = g_hrep[(SEQ8 - 1) & 1][0];
        float s = 0.f;
        for (int j = tid; j < HID; j += RTHREADS) s += __ldcg(&hf[j]) * Wh2o[j];
#pragma unroll
        for (int o = 16; o > 0; o >>= 1) s += __shfl_xor_sync(0xffffffffu, s, o);
        __syncthreads();
        if (l == 0) sred[w] = s;
        __syncthreads();
        if (tid == 0) {
            float tot = 0.f;
#pragma unroll
            for (int i = 0; i < RTHREADS / 32; i++) tot += sred[i];
            tot += bh2o[0];
            out[0] = 1.f / (1.f + expf(-tot));
        }
    }
}

// ---------------- launch ---------------------------------------------------
extern "C" void kernel_launch(void* const* d_in, const int* in_sizes, int n_in,
                              void* d_out, int out_size) {
    const int*   toks = (const int*)d_in[0];
    const float* emb  = (const float*)d_in[1];
    const float* Wi2h = (const float*)d_in[2];
    const float* bi2h = (const float*)d_in[3];
    const float* Wh2o = (const float*)d_in[4];
    const float* bh2o = (const float*)d_in[5];
    float* out = (float*)d_out;

    float* gX;  cudaGetSymbolAddress((void**)&gX,  g_X);
    float* gX2; cudaGetSymbolAddress((void**)&gX2, g_X2);
    float* gX4; cudaGetSymbolAddress((void**)&gX4, g_X4);
    float* gX8; cudaGetSymbolAddress((void**)&gX8, g_X8);
    float* gW2; cudaGetSymbolAddress((void**)&gW2, g_W2);
    float* gW4; cudaGetSymbolAddress((void**)&gW4, g_W4);
    float* gW8; cudaGetSymbolAddress((void**)&gW8, g_W8);

    reset_kernel<<<1, 32>>>();
    detect_tok_kernel<<<1, 256>>>(toks);
    gemm_x_kernel<<<dim3(HID / BN, SEQ / BM), GTHREADS>>>(toks, emb, Wi2h, bi2h);
    gemm_sq_kernel<WSTRIDE, EMB><<<dim3(HID / BN, HID / BM), GTHREADS>>>(Wi2h, gW2);
    gemm_fold_kernel<WSTRIDE, EMB><<<dim3(HID / BN, SEQ2 / BM), GTHREADS>>>(Wi2h, gX, gX2);
    gemm_sq_kernel<HID, 0><<<dim3(HID / BN, HID / BM), GTHREADS>>>(gW2, gW4);
    gemm_fold_kernel<HID, 0><<<dim3(HID / BN, SEQ4 / BM), GTHREADS>>>(gW2, gX2, gX4);
    gemm_sq_kernel<HID, 0><<<dim3(HID / BN, HID / BM), GTHREADS>>>(gW4, gW8);
    gemm_fold_kernel<HID, 0><<<dim3(HID / BN, SEQ8 / BM), GTHREADS>>>(gW4, gX4, gX8);
    rnn_kernel<<<NCTA, RTHREADS>>>(Wh2o, bh2o, out);
}